// round 8
// baseline (speedup 1.0000x reference)
#include <cuda_runtime.h>
#include <math.h>

#define N_TOK 8192
#define E_NUM 16
#define TOPK 2
#define DIN 1024
#define D_HID 4096
#define DOUT 1024
#define NP (N_TOK * TOPK)   // 16384 token-expert pairs
#define MAXT 288            // max M-tiles (<= 16384/64 + 16 = 272)

#define OUT_GL ((size_t)N_TOK * DOUT)
#define OUT_IDX (OUT_GL + (size_t)N_TOK * E_NUM)
#define OUT_TOTAL (OUT_IDX + (size_t)N_TOK * TOPK)

// ---------------- device scratch (no allocations allowed) ----------------
__device__ float g_h[(size_t)NP * D_HID];   // 256 MB: relu(xW1+b1), sorted order
__device__ float g_yw[(size_t)NP * DOUT];   // 64 MB: weight * (hW2+b2), per pair
__device__ int   g_sorted[NP];
__device__ int   g_eid[NP];
__device__ float g_wt[NP];
__device__ int   g_cnt[E_NUM];
__device__ int   g_cur[E_NUM];
__device__ int   g_off[E_NUM + 1];
__device__ int   g_tile_e[MAXT];
__device__ int   g_tile_r[MAXT];
__device__ int   g_ntiles;

// ---------------- packed f32x2 helpers ----------------
__device__ __forceinline__ void fma2(unsigned long long& d,
                                     unsigned long long a, unsigned long long b) {
    asm("fma.rn.f32x2 %0, %1, %2, %3;" : "=l"(d) : "l"(a), "l"(b), "l"(d));
}
__device__ __forceinline__ float2 unpk(unsigned long long v) {
    float2 r;
    asm("mov.b64 {%0, %1}, %2;" : "=f"(r.x), "=f"(r.y) : "l"(v));
    return r;
}

// ---------------- reset ----------------
__global__ void k_reset() {
    int t = threadIdx.x;
    if (t < E_NUM) { g_cnt[t] = 0; g_cur[t] = 0; }
    if (t == 0) g_ntiles = 0;
}

// ---------------- gating: logits, top-2, softmax ----------------
__global__ void k_gating(const float* __restrict__ x,
                         const float* __restrict__ Wg,
                         const float* __restrict__ bg,
                         const float* __restrict__ bias,
                         float* __restrict__ out,
                         int write_extra) {
    __shared__ float sx[16][256];
    __shared__ float slog[16][16];
    __shared__ float sbias[16];

    int tid = threadIdx.x;
    int tl = tid >> 4;
    int e  = tid & 15;
    int tok0 = blockIdx.x * 16;
    int token = tok0 + tl;

    if (tid < E_NUM) sbias[tid] = bias[tid];

    float acc = 0.f;
    for (int k0 = 0; k0 < DIN; k0 += 256) {
        __syncthreads();
        #pragma unroll
        for (int i = 0; i < 4; i++) {
            int lin4 = i * 1024 + tid * 4;
            int row = lin4 >> 8;
            int col = lin4 & 255;
            *(float4*)&sx[row][col] =
                *(const float4*)(x + (size_t)(tok0 + row) * DIN + k0 + col);
        }
        __syncthreads();
        #pragma unroll 8
        for (int k = 0; k < 256; k++)
            acc += sx[tl][k] * Wg[(size_t)(k0 + k) * E_NUM + e];
    }
    acc += bg[e];

    if (write_extra)
        out[OUT_GL + (size_t)token * E_NUM + e] = acc;
    slog[tl][e] = acc;
    __syncthreads();

    if (e == 0) {
        float b0 = -INFINITY; int i0 = 0;
        #pragma unroll
        for (int j = 0; j < E_NUM; j++) {
            float v = slog[tl][j] + sbias[j];
            if (v > b0) { b0 = v; i0 = j; }
        }
        float b1v = -INFINITY; int i1 = 0;
        #pragma unroll
        for (int j = 0; j < E_NUM; j++) {
            if (j == i0) continue;
            float v = slog[tl][j] + sbias[j];
            if (v > b1v) { b1v = v; i1 = j; }
        }
        float l0 = slog[tl][i0], l1 = slog[tl][i1];
        float m = fmaxf(l0, l1);
        float e0 = expf(l0 - m), e1 = expf(l1 - m);
        float inv = 1.f / (e0 + e1);
        float w0 = e0 * inv, w1 = e1 * inv;

        int p0 = token * 2, p1 = token * 2 + 1;
        g_eid[p0] = i0; g_wt[p0] = w0;
        g_eid[p1] = i1; g_wt[p1] = w1;
        atomicAdd(&g_cnt[i0], 1);
        atomicAdd(&g_cnt[i1], 1);
        if (write_extra) {
            out[OUT_IDX + p0] = (float)i0;
            out[OUT_IDX + p1] = (float)i1;
        }
    }
}

// ---------------- scan + tile map ----------------
__global__ void k_scan() {
    int off = 0;
    g_off[0] = 0;
    for (int e = 0; e < E_NUM; e++) { off += g_cnt[e]; g_off[e + 1] = off; }
    int nt = 0;
    for (int e = 0; e < E_NUM; e++)
        for (int r = 0; r < g_cnt[e]; r += 64) {
            g_tile_e[nt] = e; g_tile_r[nt] = r; nt++;
        }
    g_ntiles = nt;
}

// ---------------- scatter ----------------
__global__ void k_scatter() {
    int p = blockIdx.x * 256 + threadIdx.x;
    if (p >= NP) return;
    int e = g_eid[p];
    int pos = g_off[e] + atomicAdd(&g_cur[e], 1);
    g_sorted[pos] = p;
}

// ---------------- GEMM1: h = relu(gather(x) @ W1[e] + b1[e]), f32x2 core ----------------
__global__ void __launch_bounds__(256) k_gemm1(const float* __restrict__ x,
                                               const float* __restrict__ W1,
                                               const float* __restrict__ b1) {
    int tm = blockIdx.y;
    if (tm >= g_ntiles) return;
    int e = g_tile_e[tm], r0 = g_tile_r[tm];
    int base = g_off[e], cnt = g_cnt[e];
    int n0 = blockIdx.x * 64;

    __shared__ float As[16][68];    // [k][m]; row 272B, 16B-aligned
    __shared__ float Bs2[16][128];  // [k][2n], duplicated pairs (b,b)
    __shared__ int s_tok[64];

    int tid = threadIdx.x;
    if (tid < 64) {
        int lr = r0 + tid;
        s_tok[tid] = (lr < cnt) ? (g_sorted[base + lr] >> 1) : -1;
    }
    __syncthreads();

    const float* Wb = W1 + (size_t)e * DIN * D_HID;
    int tx = tid & 15, ty = tid >> 4;
    int arow = tid >> 2, akq = (tid & 3) * 4;    // A loader
    int bnc = (tid & 15) * 4, bkr = tid >> 4;    // B loader

    int tokA = s_tok[arow];
    const float* Arow = (tokA >= 0) ? (x + (size_t)tokA * DIN) : x;
    bool aValid = (tokA >= 0);

    unsigned long long accp[2][4] = {};   // [m-pair][n]: lo=m even, hi=m odd

    for (int k0 = 0; k0 < DIN; k0 += 16) {
        float4 av = aValid ? *(const float4*)(Arow + k0 + akq)
                           : make_float4(0.f, 0.f, 0.f, 0.f);
        float4 bv = *(const float4*)(Wb + (size_t)(k0 + bkr) * D_HID + n0 + bnc);
        __syncthreads();
        As[akq + 0][arow] = av.x; As[akq + 1][arow] = av.y;
        As[akq + 2][arow] = av.z; As[akq + 3][arow] = av.w;
        *(float4*)&Bs2[bkr][bnc * 2]     = make_float4(bv.x, bv.x, bv.y, bv.y);
        *(float4*)&Bs2[bkr][bnc * 2 + 4] = make_float4(bv.z, bv.z, bv.w, bv.w);
        __syncthreads();
        #pragma unroll
        for (int kk = 0; kk < 16; kk++) {
            ulonglong2 au  = *(const ulonglong2*)&As[kk][ty * 4];
            ulonglong2 bu0 = *(const ulonglong2*)&Bs2[kk][tx * 8];
            ulonglong2 bu1 = *(const ulonglong2*)&Bs2[kk][tx * 8 + 4];
            fma2(accp[0][0], au.x, bu0.x); fma2(accp[0][1], au.x, bu0.y);
            fma2(accp[0][2], au.x, bu1.x); fma2(accp[0][3], au.x, bu1.y);
            fma2(accp[1][0], au.y, bu0.x); fma2(accp[1][1], au.y, bu0.y);
            fma2(accp[1][2], au.y, bu1.x); fma2(accp[1][3], au.y, bu1.y);
        }
    }

    float4 bb = *(const float4*)(b1 + (size_t)e * D_HID + n0 + tx * 4);
    float bbs[4] = {bb.x, bb.y, bb.z, bb.w};
    #pragma unroll
    for (int i = 0; i < 4; i++) {
        int lr = r0 + ty * 4 + i;
        if (lr < cnt) {
            float a0, a1, a2, a3;
            {
                float2 f0 = unpk(accp[i >> 1][0]);
                float2 f1 = unpk(accp[i >> 1][1]);
                float2 f2 = unpk(accp[i >> 1][2]);
                float2 f3 = unpk(accp[i >> 1][3]);
                if (i & 1) { a0 = f0.y; a1 = f1.y; a2 = f2.y; a3 = f3.y; }
                else       { a0 = f0.x; a1 = f1.x; a2 = f2.x; a3 = f3.x; }
            }
            float4 v;
            v.x = fmaxf(a0 + bbs[0], 0.f);
            v.y = fmaxf(a1 + bbs[1], 0.f);
            v.z = fmaxf(a2 + bbs[2], 0.f);
            v.w = fmaxf(a3 + bbs[3], 0.f);
            *(float4*)(g_h + (size_t)(base + lr) * D_HID + n0 + tx * 4) = v;
        }
    }
}

// ---------------- GEMM2: yw[pair] = wt * (h @ W2[e] + b2[e]), f32x2 core ----------------
__global__ void __launch_bounds__(256) k_gemm2(const float* __restrict__ W2,
                                               const float* __restrict__ b2) {
    int tm = blockIdx.y;
    if (tm >= g_ntiles) return;
    int e = g_tile_e[tm], r0 = g_tile_r[tm];
    int base = g_off[e], cnt = g_cnt[e];
    int n0 = blockIdx.x * 64;

    __shared__ float As[16][68];
    __shared__ float Bs2[16][128];
    __shared__ int s_pair[64];

    int tid = threadIdx.x;
    if (tid < 64) {
        int lr = r0 + tid;
        s_pair[tid] = (lr < cnt) ? g_sorted[base + lr] : -1;
    }
    __syncthreads();

    const float* Wb = W2 + (size_t)e * D_HID * DOUT;
    int tx = tid & 15, ty = tid >> 4;
    int arow = tid >> 2, akq = (tid & 3) * 4;
    int bnc = (tid & 15) * 4, bkr = tid >> 4;

    int lrA = r0 + arow;
    const float* Arow = g_h + (size_t)(base + ((lrA < cnt) ? lrA : 0)) * D_HID;

    unsigned long long accp[2][4] = {};

    for (int k0 = 0; k0 < D_HID; k0 += 16) {
        float4 av = *(const float4*)(Arow + k0 + akq);
        float4 bv = *(const float4*)(Wb + (size_t)(k0 + bkr) * DOUT + n0 + bnc);
        __syncthreads();
        As[akq + 0][arow] = av.x; As[akq + 1][arow] = av.y;
        As[akq + 2][arow] = av.z; As[akq + 3][arow] = av.w;
        *(float4*)&Bs2[bkr][bnc * 2]     = make_float4(bv.x, bv.x, bv.y, bv.y);
        *(float4*)&Bs2[bkr][bnc * 2 + 4] = make_float4(bv.z, bv.z, bv.w, bv.w);
        __syncthreads();
        #pragma unroll
        for (int kk = 0; kk < 16; kk++) {
            ulonglong2 au  = *(const ulonglong2*)&As[kk][ty * 4];
            ulonglong2 bu0 = *(const ulonglong2*)&Bs2[kk][tx * 8];
            ulonglong2 bu1 = *(const ulonglong2*)&Bs2[kk][tx * 8 + 4];
            fma2(accp[0][0], au.x, bu0.x); fma2(accp[0][1], au.x, bu0.y);
            fma2(accp[0][2], au.x, bu1.x); fma2(accp[0][3], au.x, bu1.y);
            fma2(accp[1][0], au.y, bu0.x); fma2(accp[1][1], au.y, bu0.y);
            fma2(accp[1][2], au.y, bu1.x); fma2(accp[1][3], au.y, bu1.y);
        }
    }

    float4 bb = *(const float4*)(b2 + (size_t)e * DOUT + n0 + tx * 4);
    float bbs[4] = {bb.x, bb.y, bb.z, bb.w};
    #pragma unroll
    for (int i = 0; i < 4; i++) {
        int lr = r0 + ty * 4 + i;
        if (lr < cnt) {
            int pair = s_pair[ty * 4 + i];
            float w = g_wt[pair];
            float a0, a1, a2, a3;
            {
                float2 f0 = unpk(accp[i >> 1][0]);
                float2 f1 = unpk(accp[i >> 1][1]);
                float2 f2 = unpk(accp[i >> 1][2]);
                float2 f3 = unpk(accp[i >> 1][3]);
                if (i & 1) { a0 = f0.y; a1 = f1.y; a2 = f2.y; a3 = f3.y; }
                else       { a0 = f0.x; a1 = f1.x; a2 = f2.x; a3 = f3.x; }
            }
            float4 v;
            v.x = w * (a0 + bbs[0]);
            v.y = w * (a1 + bbs[1]);
            v.z = w * (a2 + bbs[2]);
            v.w = w * (a3 + bbs[3]);
            *(float4*)(g_yw + (size_t)pair * DOUT + n0 + tx * 4) = v;
        }
    }
}

// ---------------- combine: out[t] = yw[2t] + yw[2t+1] ----------------
__global__ void k_combine(float* __restrict__ out) {
    int i = blockIdx.x * 256 + threadIdx.x;
    const int C = DOUT / 4;
    int t = i >> 8;
    int c = i & 255;
    const float4* yw = (const float4*)g_yw;
    float4 u = yw[(size_t)(2 * t) * C + c];
    float4 v = yw[(size_t)(2 * t + 1) * C + c];
    float4 r;
    r.x = u.x + v.x; r.y = u.y + v.y; r.z = u.z + v.z; r.w = u.w + v.w;
    ((float4*)out)[i] = r;
}

// ---------------- launch ----------------
extern "C" void kernel_launch(void* const* d_in, const int* in_sizes, int n_in,
                              void* d_out, int out_size) {
    const float* x    = (const float*)d_in[0];
    const float* Wg   = (const float*)d_in[1];
    const float* bg   = (const float*)d_in[2];
    const float* W1   = (const float*)d_in[3];
    const float* b1   = (const float*)d_in[4];
    const float* W2   = (const float*)d_in[5];
    const float* b2   = (const float*)d_in[6];
    const float* bias = (const float*)d_in[7];
    float* out = (float*)d_out;

    int write_extra = ((size_t)out_size >= OUT_TOTAL) ? 1 : 0;

    k_reset<<<1, 32>>>();
    k_gating<<<N_TOK / 16, 256>>>(x, Wg, bg, bias, out, write_extra);
    k_scan<<<1, 1>>>();
    k_scatter<<<NP / 256, 256>>>();
    k_gemm1<<<dim3(D_HID / 64, MAXT), 256>>>(x, W1, b1);
    k_gemm2<<<dim3(DOUT / 64, MAXT), 256>>>(W2, b2);
    k_combine<<<(N_TOK * DOUT / 4) / 256, 256>>>(out);
}

// round 9
// speedup vs baseline: 3.6346x; 3.6346x over previous
#include <cuda_runtime.h>
#include <cuda_bf16.h>
#include <math.h>
#include <stdint.h>

#define N_TOK 8192
#define E_NUM 16
#define TOPK 2
#define DIN 1024
#define DHID 4096
#define DOUT 1024
#define NP (N_TOK * TOPK)
#define MAXT 160

#define OUT_GL ((size_t)N_TOK * DOUT)
#define OUT_IDX (OUT_GL + (size_t)N_TOK * E_NUM)
#define OUT_TOTAL (OUT_IDX + (size_t)N_TOK * TOPK)

// ---- GEMM tiling ----
#define BM 128
#define BN 128
#define BK 16
#define PADH 20   // halves per smem row (16 data + 4 pad)

// -------- device scratch (referenced ONLY inside kernels; never passed as args) --------
__device__ __align__(256) float g_h[((size_t)NP + BM) * DHID];
__device__ int   g_sorted[NP];
__device__ int   g_eid[NP];
__device__ float g_wt[NP];
__device__ int   g_cnt[E_NUM];
__device__ int   g_cur[E_NUM];
__device__ int   g_off[E_NUM + 1];
__device__ int   g_tile_e[MAXT];
__device__ int   g_tile_r[MAXT];
__device__ int   g_ntiles;

// ================= helpers =================
__device__ __forceinline__ void mma_bf16(float* c,
                                         uint32_t a0, uint32_t a1, uint32_t a2, uint32_t a3,
                                         uint32_t b0, uint32_t b1) {
    asm volatile(
        "mma.sync.aligned.m16n8k16.row.col.f32.bf16.bf16.f32 "
        "{%0,%1,%2,%3}, {%4,%5,%6,%7}, {%8,%9}, {%0,%1,%2,%3};"
        : "+f"(c[0]), "+f"(c[1]), "+f"(c[2]), "+f"(c[3])
        : "r"(a0), "r"(a1), "r"(a2), "r"(a3), "r"(b0), "r"(b1));
}
__device__ __forceinline__ uint32_t packbf2(float a, float b) {
    __nv_bfloat162 t = __floats2bfloat162_rn(a, b);
    return *reinterpret_cast<uint32_t*>(&t);
}
__device__ __forceinline__ float bf16rt(float v) {
    return __bfloat162float(__float2bfloat16(v));
}

// ================= small kernels =================
__global__ void k_reset() {
    int t = threadIdx.x;
    if (t < E_NUM) { g_cnt[t] = 0; g_cur[t] = 0; }
    if (t == 0) g_ntiles = 0;
}

__global__ void k_zero(float* __restrict__ out) {
    size_t i = (size_t)blockIdx.x * 256 + threadIdx.x;
    ((float4*)out)[i] = make_float4(0.f, 0.f, 0.f, 0.f);
}

__global__ void k_gating(const float* __restrict__ x,
                         const float* __restrict__ Wg,
                         const float* __restrict__ bg,
                         const float* __restrict__ bias,
                         float* __restrict__ out,
                         int write_extra) {
    __shared__ float sx[16][256];
    __shared__ float slog[16][16];
    __shared__ float sbias[16];

    int tid = threadIdx.x;
    int tl = tid >> 4;
    int e  = tid & 15;
    int tok0 = blockIdx.x * 16;
    int token = tok0 + tl;

    if (tid < E_NUM) sbias[tid] = bias[tid];

    float acc = 0.f;
    for (int k0 = 0; k0 < DIN; k0 += 256) {
        __syncthreads();
        #pragma unroll
        for (int i = 0; i < 4; i++) {
            int lin4 = i * 1024 + tid * 4;
            int row = lin4 >> 8;
            int col = lin4 & 255;
            *(float4*)&sx[row][col] =
                *(const float4*)(x + (size_t)(tok0 + row) * DIN + k0 + col);
        }
        __syncthreads();
        #pragma unroll 8
        for (int k = 0; k < 256; k++)
            acc += sx[tl][k] * Wg[(size_t)(k0 + k) * E_NUM + e];
    }
    acc += bg[e];

    if (write_extra)
        out[OUT_GL + (size_t)token * E_NUM + e] = acc;
    slog[tl][e] = acc;
    __syncthreads();

    if (e == 0) {
        float b0 = -INFINITY; int i0 = 0;
        #pragma unroll
        for (int j = 0; j < E_NUM; j++) {
            float v = slog[tl][j] + sbias[j];
            if (v > b0) { b0 = v; i0 = j; }
        }
        float b1v = -INFINITY; int i1 = 0;
        #pragma unroll
        for (int j = 0; j < E_NUM; j++) {
            if (j == i0) continue;
            float v = slog[tl][j] + sbias[j];
            if (v > b1v) { b1v = v; i1 = j; }
        }
        float l0 = slog[tl][i0], l1 = slog[tl][i1];
        float m = fmaxf(l0, l1);
        float e0 = expf(l0 - m), e1 = expf(l1 - m);
        float inv = 1.f / (e0 + e1);

        int p0 = token * 2, p1 = token * 2 + 1;
        g_eid[p0] = i0; g_wt[p0] = e0 * inv;
        g_eid[p1] = i1; g_wt[p1] = e1 * inv;
        atomicAdd(&g_cnt[i0], 1);
        atomicAdd(&g_cnt[i1], 1);
        if (write_extra) {
            out[OUT_IDX + p0] = (float)i0;
            out[OUT_IDX + p1] = (float)i1;
        }
    }
}

__global__ void k_scan() {
    int off = 0;
    g_off[0] = 0;
    for (int e = 0; e < E_NUM; e++) { off += g_cnt[e]; g_off[e + 1] = off; }
    int nt = 0;
    for (int e = 0; e < E_NUM; e++)
        for (int r = 0; r < g_cnt[e]; r += BM)
            if (nt < MAXT) { g_tile_e[nt] = e; g_tile_r[nt] = r; nt++; }
    g_ntiles = nt;
}

__global__ void k_scatter() {
    int p = blockIdx.x * 256 + threadIdx.x;
    if (p >= NP) return;
    int e = g_eid[p];
    int pos = g_off[e] + atomicAdd(&g_cur[e], 1);
    g_sorted[pos] = p;
}

// ===== grouped GEMM: mma.sync bf16x3, on-the-fly split, direct-LDS fragments =====
// C[BM,BN] = A[BM,K] @ B[K,BN]; A: x (param) for G1, g_h (device global) for G2.
template <int KTOT, int NTOT, bool G2>
__global__ void __launch_bounds__(256, 2)
k_mma_gemm(const float* __restrict__ Aglob,
           const float* __restrict__ Bglob,
           const float* __restrict__ bvec,
           float* __restrict__ outp) {
    int tm = blockIdx.y;
    if (tm >= g_ntiles) return;

    __shared__ __nv_bfloat16 sAh[BM * PADH], sAl[BM * PADH];
    __shared__ __nv_bfloat16 sBh[BN * PADH], sBl[BN * PADH];
    __shared__ int s_pair[BM];
    __shared__ float s_wt[BM];
    __shared__ float s_bias[BN];

    int tid = threadIdx.x, lane = tid & 31, w = tid >> 5;
    int warp_m = w & 3, warp_n = w >> 2;      // 4x2 warps: 32 rows x 64 cols each

    int e = g_tile_e[tm], r0 = g_tile_r[tm];
    int base = g_off[e], cnt = g_cnt[e];
    int gbase = base + r0;
    int n0g = blockIdx.x * BN;

    if (tid < BM) {
        int lr = r0 + tid;
        int pair = (lr < cnt) ? g_sorted[base + lr] : -1;
        s_pair[tid] = pair;
        s_wt[tid] = (G2 && pair >= 0) ? g_wt[pair] : 0.f;
    }
    if (tid < BN) s_bias[tid] = bvec[(size_t)e * NTOT + n0g + tid];
    __syncthreads();

    // A source: device-global g_h for G2 (NEVER passed as host arg), param for G1.
    const float* Asrc = G2 ? (const float*)g_h : Aglob;

    int ra = tid >> 1, kq = (tid & 1) * 8;          // A staging: row, k-octet
    size_t abase;
    if (G2) abase = (size_t)(gbase + ra) * KTOT;
    else {
        int p = s_pair[ra];
        abase = (size_t)((p >= 0) ? (p >> 1) : 0) * KTOT;
    }
    int kb = tid >> 4, nb = (tid & 15) * 8;         // B staging: k-row, n-octet
    size_t bbase = ((size_t)e * KTOT + kb) * NTOT + n0g + nb;   // W[e][k][n]

    float acc[2][8][4] = {};
    const int NC = KTOT / BK;

    float4 rA0, rA1, rB0, rB1;
    auto loadg = [&](int it) {
        size_t ao = abase + (size_t)it * BK + kq;
        rA0 = *(const float4*)(Asrc + ao);
        rA1 = *(const float4*)(Asrc + ao + 4);
        size_t bo = bbase + (size_t)it * BK * NTOT;
        rB0 = *(const float4*)(Bglob + bo);
        rB1 = *(const float4*)(Bglob + bo + 4);
    };

    loadg(0);
    for (int it = 0; it < NC; it++) {
        __syncthreads();
        {   // A split + store ([m][k], k contiguous)
            float f[8] = {rA0.x, rA0.y, rA0.z, rA0.w, rA1.x, rA1.y, rA1.z, rA1.w};
            float h[8], l[8];
            #pragma unroll
            for (int j = 0; j < 8; j++) { h[j] = bf16rt(f[j]); l[j] = f[j] - h[j]; }
            int o = ra * PADH + kq;
            *(uint2*)&sAh[o]     = make_uint2(packbf2(h[0], h[1]), packbf2(h[2], h[3]));
            *(uint2*)&sAh[o + 4] = make_uint2(packbf2(h[4], h[5]), packbf2(h[6], h[7]));
            *(uint2*)&sAl[o]     = make_uint2(packbf2(l[0], l[1]), packbf2(l[2], l[3]));
            *(uint2*)&sAl[o + 4] = make_uint2(packbf2(l[4], l[5]), packbf2(l[6], l[7]));
        }
        {   // B split + transpose store ([n][k], k contiguous)
            float f[8] = {rB0.x, rB0.y, rB0.z, rB0.w, rB1.x, rB1.y, rB1.z, rB1.w};
            #pragma unroll
            for (int j = 0; j < 8; j++) {
                float h = bf16rt(f[j]);
                sBh[(nb + j) * PADH + kb] = __float2bfloat16(h);
                sBl[(nb + j) * PADH + kb] = __float2bfloat16(f[j] - h);
            }
        }
        __syncthreads();
        if (it + 1 < NC) loadg(it + 1);

        int t4 = lane >> 2, k2 = (lane & 3) * 2;
        uint32_t ah[2][4], al[2][4];
        #pragma unroll
        for (int i = 0; i < 2; i++) {
            int Rr = warp_m * 32 + i * 16 + t4;
            ah[i][0] = *(const uint32_t*)&sAh[Rr * PADH + k2];
            ah[i][1] = *(const uint32_t*)&sAh[(Rr + 8) * PADH + k2];
            ah[i][2] = *(const uint32_t*)&sAh[Rr * PADH + k2 + 8];
            ah[i][3] = *(const uint32_t*)&sAh[(Rr + 8) * PADH + k2 + 8];
            al[i][0] = *(const uint32_t*)&sAl[Rr * PADH + k2];
            al[i][1] = *(const uint32_t*)&sAl[(Rr + 8) * PADH + k2];
            al[i][2] = *(const uint32_t*)&sAl[Rr * PADH + k2 + 8];
            al[i][3] = *(const uint32_t*)&sAl[(Rr + 8) * PADH + k2 + 8];
        }
        #pragma unroll
        for (int jn = 0; jn < 8; jn++) {
            int nn = warp_n * 64 + jn * 8 + t4;
            uint32_t bh0 = *(const uint32_t*)&sBh[nn * PADH + k2];
            uint32_t bh1 = *(const uint32_t*)&sBh[nn * PADH + k2 + 8];
            uint32_t bl0 = *(const uint32_t*)&sBl[nn * PADH + k2];
            uint32_t bl1 = *(const uint32_t*)&sBl[nn * PADH + k2 + 8];
            #pragma unroll
            for (int i = 0; i < 2; i++) {
                mma_bf16(acc[i][jn], ah[i][0], ah[i][1], ah[i][2], ah[i][3], bh0, bh1);
                mma_bf16(acc[i][jn], ah[i][0], ah[i][1], ah[i][2], ah[i][3], bl0, bl1);
                mma_bf16(acc[i][jn], al[i][0], al[i][1], al[i][2], al[i][3], bh0, bh1);
            }
        }
    }

    // ---- epilogue ----
    #pragma unroll
    for (int i = 0; i < 2; i++) {
        #pragma unroll
        for (int jn = 0; jn < 8; jn++) {
            int colb = warp_n * 64 + jn * 8 + (lane & 3) * 2;
            float bb0 = s_bias[colb], bb1 = s_bias[colb + 1];
            #pragma unroll
            for (int rp = 0; rp < 2; rp++) {
                int row = warp_m * 32 + i * 16 + (lane >> 2) + 8 * rp;
                int pair = s_pair[row];
                if (pair < 0) continue;
                float v0 = acc[i][jn][2 * rp]     + bb0;
                float v1 = acc[i][jn][2 * rp + 1] + bb1;
                if (!G2) {
                    float* hp = g_h + (size_t)(gbase + row) * DHID + n0g + colb;
                    hp[0] = fmaxf(v0, 0.f);
                    hp[1] = fmaxf(v1, 0.f);
                } else {
                    int token = pair >> 1;
                    float wgt = s_wt[row];
                    float* op = outp + (size_t)token * DOUT + n0g + colb;
                    atomicAdd(op,     wgt * v0);
                    atomicAdd(op + 1, wgt * v1);
                }
            }
        }
    }
}

// ================= launch =================
extern "C" void kernel_launch(void* const* d_in, const int* in_sizes, int n_in,
                              void* d_out, int out_size) {
    const float* x    = (const float*)d_in[0];
    const float* Wg   = (const float*)d_in[1];
    const float* bg   = (const float*)d_in[2];
    const float* W1   = (const float*)d_in[3];
    const float* b1   = (const float*)d_in[4];
    const float* W2   = (const float*)d_in[5];
    const float* b2   = (const float*)d_in[6];
    const float* bias = (const float*)d_in[7];
    float* out = (float*)d_out;

    int write_extra = ((size_t)out_size >= OUT_TOTAL) ? 1 : 0;

    k_reset<<<1, 32>>>();
    k_gating<<<N_TOK / 16, 256>>>(x, Wg, bg, bias, out, write_extra);
    k_scan<<<1, 1>>>();
    k_scatter<<<NP / 256, 256>>>();
    k_zero<<<(N_TOK * DOUT / 4) / 256, 256>>>(out);

    // NOTE: only harness pointers passed as kernel args; g_h referenced in-kernel.
    k_mma_gemm<DIN, DHID, false><<<dim3(DHID / BN, MAXT), 256>>>(x, W1, b1, nullptr);
    k_mma_gemm<DHID, DOUT, true><<<dim3(DOUT / BN, MAXT), 256>>>(nullptr, W2, b2, out);
}

// round 10
// speedup vs baseline: 5.2068x; 1.4326x over previous
#include <cuda_runtime.h>
#include <cuda_bf16.h>
#include <math.h>
#include <stdint.h>

#define N_TOK 8192
#define E_NUM 16
#define TOPK 2
#define DIN 1024
#define DHID 4096
#define DOUT 1024
#define NP (N_TOK * TOPK)
#define MAXT 160

#define OUT_GL ((size_t)N_TOK * DOUT)
#define OUT_IDX (OUT_GL + (size_t)N_TOK * E_NUM)
#define OUT_TOTAL (OUT_IDX + (size_t)N_TOK * TOPK)

// ---- GEMM tiling ----
#define BM 128
#define BN 128
#define BK 16
#define PADK 24                 // halves per row (16 data + 8 pad) -> conflict-free
#define ARRB (BM * PADK * 2)    // 6144 bytes per array
#define STGB (4 * ARRB)         // 24576 bytes per stage

// -------- device scratch (referenced ONLY inside kernels; NEVER passed as args) --------
__device__ __align__(256) __nv_bfloat16 g_xhi[(size_t)N_TOK * DIN];
__device__ __align__(256) __nv_bfloat16 g_xlo[(size_t)N_TOK * DIN];
__device__ __align__(256) __nv_bfloat16 g_hhi[((size_t)NP + BM) * DHID];
__device__ __align__(256) __nv_bfloat16 g_hlo[((size_t)NP + BM) * DHID];
__device__ __align__(256) __nv_bfloat16 g_w1hi[(size_t)E_NUM * DHID * DIN]; // [e][n][k]
__device__ __align__(256) __nv_bfloat16 g_w1lo[(size_t)E_NUM * DHID * DIN];
__device__ __align__(256) __nv_bfloat16 g_w2hi[(size_t)E_NUM * DOUT * DHID];
__device__ __align__(256) __nv_bfloat16 g_w2lo[(size_t)E_NUM * DOUT * DHID];
__device__ int   g_sorted[NP];
__device__ int   g_eid[NP];
__device__ float g_wt[NP];
__device__ int   g_cnt[E_NUM];
__device__ int   g_cur[E_NUM];
__device__ int   g_off[E_NUM + 1];
__device__ int   g_tile_e[MAXT];
__device__ int   g_tile_r[MAXT];
__device__ int   g_ntiles;

// ================= helpers =================
__device__ __forceinline__ uint32_t smem_u32(const void* p) {
    uint32_t a;
    asm("{ .reg .u64 t; cvta.to.shared.u64 t, %1; cvt.u32.u64 %0, t; }"
        : "=r"(a) : "l"(p));
    return a;
}
__device__ __forceinline__ void cpa16(uint32_t dst, const void* src) {
    asm volatile("cp.async.cg.shared.global [%0], [%1], 16;"
                 :: "r"(dst), "l"(src) : "memory");
}
#define CP_COMMIT() asm volatile("cp.async.commit_group;" ::: "memory")
#define CP_WAIT1()  asm volatile("cp.async.wait_group 1;" ::: "memory")
#define CP_WAIT0()  asm volatile("cp.async.wait_group 0;" ::: "memory")

__device__ __forceinline__ void mma_bf16(float* c,
                                         uint32_t a0, uint32_t a1, uint32_t a2, uint32_t a3,
                                         uint32_t b0, uint32_t b1) {
    asm volatile(
        "mma.sync.aligned.m16n8k16.row.col.f32.bf16.bf16.f32 "
        "{%0,%1,%2,%3}, {%4,%5,%6,%7}, {%8,%9}, {%0,%1,%2,%3};"
        : "+f"(c[0]), "+f"(c[1]), "+f"(c[2]), "+f"(c[3])
        : "r"(a0), "r"(a1), "r"(a2), "r"(a3), "r"(b0), "r"(b1));
}
__device__ __forceinline__ uint32_t packbf2(float a, float b) {
    __nv_bfloat162 t = __floats2bfloat162_rn(a, b);
    return *reinterpret_cast<uint32_t*>(&t);
}
__device__ __forceinline__ float bf16rt(float v) {
    return __bfloat162float(__float2bfloat16(v));
}
__device__ __forceinline__ uint32_t ldsm32(uint32_t addr) {
    uint32_t r;
    asm volatile("ld.shared.b32 %0, [%1];" : "=r"(r) : "r"(addr));
    return r;
}

// ================= small kernels =================
__global__ void k_reset() {
    int t = threadIdx.x;
    if (t < E_NUM) { g_cnt[t] = 0; g_cur[t] = 0; }
    if (t == 0) g_ntiles = 0;
}

__global__ void k_zero(float* __restrict__ out) {
    size_t i = (size_t)blockIdx.x * 256 + threadIdx.x;
    ((float4*)out)[i] = make_float4(0.f, 0.f, 0.f, 0.f);
}

// split x fp32 -> bf16 hi/lo (symbols written in-kernel)
__global__ void k_xsplit(const float* __restrict__ x) {
    size_t i = ((size_t)blockIdx.x * 256 + threadIdx.x) * 4;
    float4 f = *(const float4*)(x + i);
    float hx = bf16rt(f.x), hy = bf16rt(f.y), hz = bf16rt(f.z), hw = bf16rt(f.w);
    *(uint2*)(g_xhi + i) = make_uint2(packbf2(hx, hy), packbf2(hz, hw));
    *(uint2*)(g_xlo + i) = make_uint2(packbf2(f.x - hx, f.y - hy),
                                      packbf2(f.z - hz, f.w - hw));
}

// transpose+split: W[e][k][n] fp32 -> hi/lo [e][n][k] bf16 (which: 0=W1, 1=W2)
__global__ void k_wsplit(const float* __restrict__ W, int K, int Nn, int which) {
    __shared__ float s[32][33];
    int e = blockIdx.z;
    int k0 = blockIdx.y * 32, n0 = blockIdx.x * 32;
    int tx = threadIdx.x, ty = threadIdx.y;   // (32,8)
    const float* Wp = W + (size_t)e * K * Nn;
    #pragma unroll
    for (int i = 0; i < 4; i++)
        s[ty + 8 * i][tx] = Wp[(size_t)(k0 + ty + 8 * i) * Nn + n0 + tx];
    __syncthreads();
    #pragma unroll
    for (int i = 0; i < 4; i++) {
        int n = n0 + ty + 8 * i;
        float v = s[tx][ty + 8 * i];
        float h = bf16rt(v);
        size_t o = ((size_t)e * Nn + n) * K + k0 + tx;
        if (which == 0) {
            g_w1hi[o] = __float2bfloat16(h);
            g_w1lo[o] = __float2bfloat16(v - h);
        } else {
            g_w2hi[o] = __float2bfloat16(h);
            g_w2lo[o] = __float2bfloat16(v - h);
        }
    }
}

__global__ void k_gating(const float* __restrict__ x,
                         const float* __restrict__ Wg,
                         const float* __restrict__ bg,
                         const float* __restrict__ bias,
                         float* __restrict__ out,
                         int write_extra) {
    __shared__ float sx[16][256];
    __shared__ float slog[16][16];
    __shared__ float sbias[16];

    int tid = threadIdx.x;
    int tl = tid >> 4;
    int e  = tid & 15;
    int tok0 = blockIdx.x * 16;
    int token = tok0 + tl;

    if (tid < E_NUM) sbias[tid] = bias[tid];

    float acc = 0.f;
    for (int k0 = 0; k0 < DIN; k0 += 256) {
        __syncthreads();
        #pragma unroll
        for (int i = 0; i < 4; i++) {
            int lin4 = i * 1024 + tid * 4;
            int row = lin4 >> 8;
            int col = lin4 & 255;
            *(float4*)&sx[row][col] =
                *(const float4*)(x + (size_t)(tok0 + row) * DIN + k0 + col);
        }
        __syncthreads();
        #pragma unroll 8
        for (int k = 0; k < 256; k++)
            acc += sx[tl][k] * Wg[(size_t)(k0 + k) * E_NUM + e];
    }
    acc += bg[e];

    if (write_extra)
        out[OUT_GL + (size_t)token * E_NUM + e] = acc;
    slog[tl][e] = acc;
    __syncthreads();

    if (e == 0) {
        float b0 = -INFINITY; int i0 = 0;
        #pragma unroll
        for (int j = 0; j < E_NUM; j++) {
            float v = slog[tl][j] + sbias[j];
            if (v > b0) { b0 = v; i0 = j; }
        }
        float b1v = -INFINITY; int i1 = 0;
        #pragma unroll
        for (int j = 0; j < E_NUM; j++) {
            if (j == i0) continue;
            float v = slog[tl][j] + sbias[j];
            if (v > b1v) { b1v = v; i1 = j; }
        }
        float l0 = slog[tl][i0], l1 = slog[tl][i1];
        float m = fmaxf(l0, l1);
        float e0 = expf(l0 - m), e1 = expf(l1 - m);
        float inv = 1.f / (e0 + e1);

        int p0 = token * 2, p1 = token * 2 + 1;
        g_eid[p0] = i0; g_wt[p0] = e0 * inv;
        g_eid[p1] = i1; g_wt[p1] = e1 * inv;
        atomicAdd(&g_cnt[i0], 1);
        atomicAdd(&g_cnt[i1], 1);
        if (write_extra) {
            out[OUT_IDX + p0] = (float)i0;
            out[OUT_IDX + p1] = (float)i1;
        }
    }
}

__global__ void k_scan() {
    int off = 0;
    g_off[0] = 0;
    for (int e = 0; e < E_NUM; e++) { off += g_cnt[e]; g_off[e + 1] = off; }
    int nt = 0;
    for (int e = 0; e < E_NUM; e++)
        for (int r = 0; r < g_cnt[e]; r += BM)
            if (nt < MAXT) { g_tile_e[nt] = e; g_tile_r[nt] = r; nt++; }
    g_ntiles = nt;
}

__global__ void k_scatter() {
    int p = blockIdx.x * 256 + threadIdx.x;
    if (p >= NP) return;
    int e = g_eid[p];
    int pos = g_off[e] + atomicAdd(&g_cur[e], 1);
    g_sorted[pos] = p;
}

// ===== grouped GEMM: cp.async 2-stage pipeline, pre-split bf16 operands =====
// C[BM,BN] = A[BM,K] @ B[N,K]^T; all operand arrays are device globals (in-kernel).
template <int KTOT, int NTOT, bool G2>
__global__ void __launch_bounds__(256, 2)
k_mma_gemm(const float* __restrict__ bvec, float* __restrict__ outp) {
    int tm = blockIdx.y;
    if (tm >= g_ntiles) return;

    // exactly 48KB: [stage][array(Ah,Al,Bh,Bl)][BM*PADK halves]
    __shared__ __nv_bfloat16 smem[2][4][BM * PADK];
    uint32_t smb = smem_u32(&smem[0][0][0]);

    int tid = threadIdx.x, lane = tid & 31, w = tid >> 5;
    int warp_m = w & 3, warp_n = w >> 2;     // 4x2 warps: 32 rows x 64 cols each

    int e = g_tile_e[tm], r0 = g_tile_r[tm];
    int base = g_off[e], cnt = g_cnt[e];
    int gbase = base + r0;
    int n0g = blockIdx.x * BN;

    // ---- staging: each thread owns one row per array, one 16B chunk ----
    int row = tid >> 1, oct = tid & 1;
    const __nv_bfloat16* Ahi = G2 ? g_hhi : g_xhi;
    const __nv_bfloat16* Alo = G2 ? g_hlo : g_xlo;
    const __nv_bfloat16* Bhi = G2 ? g_w2hi : g_w1hi;
    const __nv_bfloat16* Blo = G2 ? g_w2lo : g_w1lo;

    size_t abase;
    if (G2) {
        abase = (size_t)(gbase + row) * KTOT;
    } else {
        int lr = r0 + row;
        int p = (lr < cnt) ? g_sorted[base + lr] : -1;
        abase = (size_t)((p >= 0) ? (p >> 1) : 0) * KTOT;
    }
    size_t bbase = ((size_t)e * NTOT + n0g + row) * KTOT;
    uint32_t dstoff = (uint32_t)(row * (PADK * 2) + oct * 16);

    auto fill = [&](int s, int it) {
        uint32_t sb = smb + s * STGB;
        size_t ko = (size_t)it * BK + oct * 8;
        cpa16(sb + 0 * ARRB + dstoff, Ahi + abase + ko);
        cpa16(sb + 1 * ARRB + dstoff, Alo + abase + ko);
        cpa16(sb + 2 * ARRB + dstoff, Bhi + bbase + ko);
        cpa16(sb + 3 * ARRB + dstoff, Blo + bbase + ko);
    };

    float acc[2][8][4] = {};
    const int NC = KTOT / BK;

    fill(0, 0); CP_COMMIT();
    fill(1, 1); CP_COMMIT();

    int t4 = lane >> 2, k2b = (lane & 3) * 4;   // fragment lane offsets (bytes)

    for (int it = 0; it < NC; it++) {
        int s = it & 1;
        if (it + 2 < NC) CP_WAIT1(); else CP_WAIT0();
        __syncthreads();

        uint32_t sb = smb + s * STGB;
        uint32_t ah[2][4], al[2][4];
        #pragma unroll
        for (int i = 0; i < 2; i++) {
            uint32_t ra = sb + (uint32_t)((warp_m * 32 + i * 16 + t4) * (PADK * 2)) + k2b;
            ah[i][0] = ldsm32(ra);
            ah[i][1] = ldsm32(ra + 8 * (PADK * 2));
            ah[i][2] = ldsm32(ra + 16);
            ah[i][3] = ldsm32(ra + 8 * (PADK * 2) + 16);
            uint32_t rl = ra + ARRB;
            al[i][0] = ldsm32(rl);
            al[i][1] = ldsm32(rl + 8 * (PADK * 2));
            al[i][2] = ldsm32(rl + 16);
            al[i][3] = ldsm32(rl + 8 * (PADK * 2) + 16);
        }
        #pragma unroll
        for (int jn = 0; jn < 8; jn++) {
            uint32_t rb = sb + 2 * ARRB +
                (uint32_t)((warp_n * 64 + jn * 8 + t4) * (PADK * 2)) + k2b;
            uint32_t bh0 = ldsm32(rb);
            uint32_t bh1 = ldsm32(rb + 16);
            uint32_t bl0 = ldsm32(rb + ARRB);
            uint32_t bl1 = ldsm32(rb + ARRB + 16);
            #pragma unroll
            for (int i = 0; i < 2; i++) {
                mma_bf16(acc[i][jn], ah[i][0], ah[i][1], ah[i][2], ah[i][3], bh0, bh1);
                mma_bf16(acc[i][jn], ah[i][0], ah[i][1], ah[i][2], ah[i][3], bl0, bl1);
                mma_bf16(acc[i][jn], al[i][0], al[i][1], al[i][2], al[i][3], bh0, bh1);
            }
        }
        __syncthreads();
        if (it + 2 < NC) { fill(s, it + 2); CP_COMMIT(); }
    }

    // ---- epilogue ----
    #pragma unroll
    for (int i = 0; i < 2; i++) {
        #pragma unroll
        for (int jn = 0; jn < 8; jn++) {
            int colb = warp_n * 64 + jn * 8 + (lane & 3) * 2;
            float bb0 = bvec[(size_t)e * NTOT + n0g + colb];
            float bb1 = bvec[(size_t)e * NTOT + n0g + colb + 1];
            #pragma unroll
            for (int rp = 0; rp < 2; rp++) {
                int orow = warp_m * 32 + i * 16 + t4 + 8 * rp;
                int lr = r0 + orow;
                if (lr >= cnt) continue;
                int pair = g_sorted[base + lr];
                float v0 = acc[i][jn][2 * rp]     + bb0;
                float v1 = acc[i][jn][2 * rp + 1] + bb1;
                if (!G2) {
                    v0 = fmaxf(v0, 0.f);
                    v1 = fmaxf(v1, 0.f);
                    float h0 = bf16rt(v0), h1 = bf16rt(v1);
                    size_t o = (size_t)(gbase + orow) * DHID + n0g + colb;
                    *(uint32_t*)&g_hhi[o] = packbf2(h0, h1);
                    *(uint32_t*)&g_hlo[o] = packbf2(v0 - h0, v1 - h1);
                } else {
                    int token = pair >> 1;
                    float wgt = g_wt[pair];
                    float* op = outp + (size_t)token * DOUT + n0g + colb;
                    atomicAdd(op,     wgt * v0);
                    atomicAdd(op + 1, wgt * v1);
                }
            }
        }
    }
}

// ================= launch =================
extern "C" void kernel_launch(void* const* d_in, const int* in_sizes, int n_in,
                              void* d_out, int out_size) {
    const float* x    = (const float*)d_in[0];
    const float* Wg   = (const float*)d_in[1];
    const float* bg   = (const float*)d_in[2];
    const float* W1   = (const float*)d_in[3];
    const float* b1   = (const float*)d_in[4];
    const float* W2   = (const float*)d_in[5];
    const float* b2   = (const float*)d_in[6];
    const float* bias = (const float*)d_in[7];
    float* out = (float*)d_out;

    int write_extra = ((size_t)out_size >= OUT_TOTAL) ? 1 : 0;

    k_reset<<<1, 32>>>();
    k_gating<<<N_TOK / 16, 256>>>(x, Wg, bg, bias, out, write_extra);
    k_scan<<<1, 1>>>();
    k_scatter<<<NP / 256, 256>>>();
    k_zero<<<(N_TOK * DOUT / 4) / 256, 256>>>(out);
    k_xsplit<<<(N_TOK * DIN / 4) / 256, 256>>>(x);
    k_wsplit<<<dim3(DHID / 32, DIN / 32, E_NUM), dim3(32, 8)>>>(W1, DIN, DHID, 0);
    k_wsplit<<<dim3(DOUT / 32, DHID / 32, E_NUM), dim3(32, 8)>>>(W2, DHID, DOUT, 1);

    k_mma_gemm<DIN, DHID, false><<<dim3(DHID / BN, MAXT), 256>>>(b1, nullptr);
    k_mma_gemm<DHID, DOUT, true><<<dim3(DOUT / BN, MAXT), 256>>>(b2, out);
}

// round 11
// speedup vs baseline: 5.8225x; 1.1182x over previous
#include <cuda_runtime.h>
#include <cuda_bf16.h>
#include <math.h>
#include <stdint.h>

#define N_TOK 8192
#define E_NUM 16
#define TOPK 2
#define DIN 1024
#define DHID 4096
#define DOUT 1024
#define NP (N_TOK * TOPK)
#define MAXT 160

#define OUT_GL ((size_t)N_TOK * DOUT)
#define OUT_IDX (OUT_GL + (size_t)N_TOK * E_NUM)
#define OUT_TOTAL (OUT_IDX + (size_t)N_TOK * TOPK)

// ---- GEMM tiling ----
#define BM 128
#define BN 128
#define BK 16
#define PADK 24                 // halves per row -> 48B stride, ldmatrix conflict-free
#define ROWB (PADK * 2)         // 48 bytes
#define ARRB (BM * ROWB)        // 6144 bytes per array
#define STGB (4 * ARRB)         // 24576 bytes per stage

// -------- device scratch (referenced ONLY inside kernels; NEVER passed as args) --------
__device__ __align__(256) __nv_bfloat16 g_xhi[(size_t)N_TOK * DIN];
__device__ __align__(256) __nv_bfloat16 g_xlo[(size_t)N_TOK * DIN];
__device__ __align__(256) __nv_bfloat16 g_hhi[((size_t)NP + BM) * DHID];
__device__ __align__(256) __nv_bfloat16 g_hlo[((size_t)NP + BM) * DHID];
__device__ __align__(256) __nv_bfloat16 g_w1hi[(size_t)E_NUM * DHID * DIN]; // [e][n][k]
__device__ __align__(256) __nv_bfloat16 g_w1lo[(size_t)E_NUM * DHID * DIN];
__device__ __align__(256) __nv_bfloat16 g_w2hi[(size_t)E_NUM * DOUT * DHID];
__device__ __align__(256) __nv_bfloat16 g_w2lo[(size_t)E_NUM * DOUT * DHID];
__device__ int   g_sorted[NP];
__device__ int   g_eid[NP];
__device__ float g_wt[NP];
__device__ int   g_cnt[E_NUM];
__device__ int   g_cur[E_NUM];
__device__ int   g_off[E_NUM + 1];
__device__ int   g_tile_e[MAXT];
__device__ int   g_tile_r[MAXT];
__device__ int   g_ntiles;

// ================= helpers =================
__device__ __forceinline__ uint32_t smem_u32(const void* p) {
    uint32_t a;
    asm("{ .reg .u64 t; cvta.to.shared.u64 t, %1; cvt.u32.u64 %0, t; }"
        : "=r"(a) : "l"(p));
    return a;
}
__device__ __forceinline__ void cpa16(uint32_t dst, const void* src) {
    asm volatile("cp.async.cg.shared.global [%0], [%1], 16;"
                 :: "r"(dst), "l"(src) : "memory");
}
#define CP_COMMIT() asm volatile("cp.async.commit_group;" ::: "memory")
#define CP_WAIT1()  asm volatile("cp.async.wait_group 1;" ::: "memory")
#define CP_WAIT0()  asm volatile("cp.async.wait_group 0;" ::: "memory")

__device__ __forceinline__ void ldsm_x4(uint32_t* r, uint32_t addr) {
    asm volatile("ldmatrix.sync.aligned.m8n8.x4.shared.b16 {%0,%1,%2,%3}, [%4];"
        : "=r"(r[0]), "=r"(r[1]), "=r"(r[2]), "=r"(r[3]) : "r"(addr));
}
__device__ __forceinline__ void mma_bf16(float* c, const uint32_t* a,
                                         uint32_t b0, uint32_t b1) {
    asm volatile(
        "mma.sync.aligned.m16n8k16.row.col.f32.bf16.bf16.f32 "
        "{%0,%1,%2,%3}, {%4,%5,%6,%7}, {%8,%9}, {%0,%1,%2,%3};"
        : "+f"(c[0]), "+f"(c[1]), "+f"(c[2]), "+f"(c[3])
        : "r"(a[0]), "r"(a[1]), "r"(a[2]), "r"(a[3]), "r"(b0), "r"(b1));
}
__device__ __forceinline__ uint32_t packbf2(float a, float b) {
    __nv_bfloat162 t = __floats2bfloat162_rn(a, b);
    return *reinterpret_cast<uint32_t*>(&t);
}
__device__ __forceinline__ float bf16rt(float v) {
    return __bfloat162float(__float2bfloat16(v));
}

// ================= small kernels =================
__global__ void k_reset() {
    int t = threadIdx.x;
    if (t < E_NUM) { g_cnt[t] = 0; g_cur[t] = 0; }
    if (t == 0) g_ntiles = 0;
}

__global__ void k_zero(float* __restrict__ out) {
    size_t i = (size_t)blockIdx.x * 256 + threadIdx.x;
    ((float4*)out)[i] = make_float4(0.f, 0.f, 0.f, 0.f);
}

__global__ void k_xsplit(const float* __restrict__ x) {
    size_t i = ((size_t)blockIdx.x * 256 + threadIdx.x) * 4;
    float4 f = *(const float4*)(x + i);
    float hx = bf16rt(f.x), hy = bf16rt(f.y), hz = bf16rt(f.z), hw = bf16rt(f.w);
    *(uint2*)(g_xhi + i) = make_uint2(packbf2(hx, hy), packbf2(hz, hw));
    *(uint2*)(g_xlo + i) = make_uint2(packbf2(f.x - hx, f.y - hy),
                                      packbf2(f.z - hz, f.w - hw));
}

// transpose+split: W[e][k][n] fp32 -> hi/lo [e][n][k] bf16
__global__ void k_wsplit(const float* __restrict__ W, int K, int Nn, int which) {
    __shared__ float s[32][33];
    int e = blockIdx.z;
    int k0 = blockIdx.y * 32, n0 = blockIdx.x * 32;
    int tx = threadIdx.x, ty = threadIdx.y;   // (32,8)
    const float* Wp = W + (size_t)e * K * Nn;
    #pragma unroll
    for (int i = 0; i < 4; i++)
        s[ty + 8 * i][tx] = Wp[(size_t)(k0 + ty + 8 * i) * Nn + n0 + tx];
    __syncthreads();
    #pragma unroll
    for (int i = 0; i < 4; i++) {
        int n = n0 + ty + 8 * i;
        float v = s[tx][ty + 8 * i];
        float h = bf16rt(v);
        size_t o = ((size_t)e * Nn + n) * K + k0 + tx;
        if (which == 0) {
            g_w1hi[o] = __float2bfloat16(h);
            g_w1lo[o] = __float2bfloat16(v - h);
        } else {
            g_w2hi[o] = __float2bfloat16(h);
            g_w2lo[o] = __float2bfloat16(v - h);
        }
    }
}

__global__ void k_gating(const float* __restrict__ x,
                         const float* __restrict__ Wg,
                         const float* __restrict__ bg,
                         const float* __restrict__ bias,
                         float* __restrict__ out,
                         int write_extra) {
    __shared__ float sx[16][256];
    __shared__ float slog[16][16];
    __shared__ float sbias[16];

    int tid = threadIdx.x;
    int tl = tid >> 4;
    int e  = tid & 15;
    int tok0 = blockIdx.x * 16;
    int token = tok0 + tl;

    if (tid < E_NUM) sbias[tid] = bias[tid];

    float acc = 0.f;
    for (int k0 = 0; k0 < DIN; k0 += 256) {
        __syncthreads();
        #pragma unroll
        for (int i = 0; i < 4; i++) {
            int lin4 = i * 1024 + tid * 4;
            int row = lin4 >> 8;
            int col = lin4 & 255;
            *(float4*)&sx[row][col] =
                *(const float4*)(x + (size_t)(tok0 + row) * DIN + k0 + col);
        }
        __syncthreads();
        #pragma unroll 8
        for (int k = 0; k < 256; k++)
            acc += sx[tl][k] * Wg[(size_t)(k0 + k) * E_NUM + e];
    }
    acc += bg[e];

    if (write_extra)
        out[OUT_GL + (size_t)token * E_NUM + e] = acc;
    slog[tl][e] = acc;
    __syncthreads();

    if (e == 0) {
        float b0 = -INFINITY; int i0 = 0;
        #pragma unroll
        for (int j = 0; j < E_NUM; j++) {
            float v = slog[tl][j] + sbias[j];
            if (v > b0) { b0 = v; i0 = j; }
        }
        float b1v = -INFINITY; int i1 = 0;
        #pragma unroll
        for (int j = 0; j < E_NUM; j++) {
            if (j == i0) continue;
            float v = slog[tl][j] + sbias[j];
            if (v > b1v) { b1v = v; i1 = j; }
        }
        float l0 = slog[tl][i0], l1 = slog[tl][i1];
        float m = fmaxf(l0, l1);
        float e0 = expf(l0 - m), e1 = expf(l1 - m);
        float inv = 1.f / (e0 + e1);

        int p0 = token * 2, p1 = token * 2 + 1;
        g_eid[p0] = i0; g_wt[p0] = e0 * inv;
        g_eid[p1] = i1; g_wt[p1] = e1 * inv;
        atomicAdd(&g_cnt[i0], 1);
        atomicAdd(&g_cnt[i1], 1);
        if (write_extra) {
            out[OUT_IDX + p0] = (float)i0;
            out[OUT_IDX + p1] = (float)i1;
        }
    }
}

__global__ void k_scan() {
    int off = 0;
    g_off[0] = 0;
    for (int e = 0; e < E_NUM; e++) { off += g_cnt[e]; g_off[e + 1] = off; }
    int nt = 0;
    for (int e = 0; e < E_NUM; e++)
        for (int r = 0; r < g_cnt[e]; r += BM)
            if (nt < MAXT) { g_tile_e[nt] = e; g_tile_r[nt] = r; nt++; }
    g_ntiles = nt;
}

__global__ void k_scatter() {
    int p = blockIdx.x * 256 + threadIdx.x;
    if (p >= NP) return;
    int e = g_eid[p];
    int pos = g_off[e] + atomicAdd(&g_cur[e], 1);
    g_sorted[pos] = p;
}

// ===== grouped GEMM: cp.async 2-stage + ldmatrix fragments, pre-split bf16 =====
template <int KTOT, int NTOT, bool G2>
__global__ void __launch_bounds__(256, 2)
k_mma_gemm(const float* __restrict__ bvec, float* __restrict__ outp) {
    int tm = blockIdx.y;
    if (tm >= g_ntiles) return;

    __shared__ __nv_bfloat16 smem[2][4][BM * PADK];   // 48KB
    uint32_t smb = smem_u32(&smem[0][0][0]);

    int tid = threadIdx.x, lane = tid & 31, w = tid >> 5;
    int warp_m = w & 3, warp_n = w >> 2;     // 4x2 warps: 32 rows x 64 cols each

    int e = g_tile_e[tm], r0 = g_tile_r[tm];
    int base = g_off[e], cnt = g_cnt[e];
    int gbase = base + r0;
    int n0g = blockIdx.x * BN;

    // ---- staging ----
    int row = tid >> 1, oct = tid & 1;
    const __nv_bfloat16* Ahi = G2 ? g_hhi : g_xhi;
    const __nv_bfloat16* Alo = G2 ? g_hlo : g_xlo;
    const __nv_bfloat16* Bhi = G2 ? g_w2hi : g_w1hi;
    const __nv_bfloat16* Blo = G2 ? g_w2lo : g_w1lo;

    size_t abase;
    if (G2) {
        abase = (size_t)(gbase + row) * KTOT;
    } else {
        int lr = r0 + row;
        int p = (lr < cnt) ? g_sorted[base + lr] : -1;
        abase = (size_t)((p >= 0) ? (p >> 1) : 0) * KTOT;
    }
    size_t bbase = ((size_t)e * NTOT + n0g + row) * KTOT;
    uint32_t dstoff = (uint32_t)(row * ROWB + oct * 16);

    auto fill = [&](int s, int it) {
        uint32_t sb = smb + s * STGB;
        size_t ko = (size_t)it * BK + oct * 8;
        cpa16(sb + 0 * ARRB + dstoff, Ahi + abase + ko);
        cpa16(sb + 1 * ARRB + dstoff, Alo + abase + ko);
        cpa16(sb + 2 * ARRB + dstoff, Bhi + bbase + ko);
        cpa16(sb + 3 * ARRB + dstoff, Blo + bbase + ko);
    };

    float acc[2][8][4] = {};
    const int NC = KTOT / BK;

    fill(0, 0); CP_COMMIT();
    fill(1, 1); CP_COMMIT();

    // ldmatrix lane-relative offsets
    int lq = lane >> 3, lr8 = lane & 7;
    // A x4: m0 rows 0-7 @k0 | m1 rows 8-15 @k0 | m2 rows 0-7 @k8 | m3 rows 8-15 @k8
    uint32_t arel = (uint32_t)((lr8 + (lq & 1) * 8) * ROWB + (lq >> 1) * 16);
    // B x4: m0 n0-7 @k0 | m1 n0-7 @k8 | m2 n8-15 @k0 | m3 n8-15 @k8
    uint32_t brel = (uint32_t)((lr8 + (lq >> 1) * 8) * ROWB + (lq & 1) * 16);

    int t4 = lane >> 2;

    for (int it = 0; it < NC; it++) {
        int s = it & 1;
        if (it + 2 < NC) CP_WAIT1(); else CP_WAIT0();
        __syncthreads();

        uint32_t sb = smb + s * STGB;
        uint32_t ah[2][4], al[2][4];
        #pragma unroll
        for (int i = 0; i < 2; i++) {
            uint32_t ra = sb + (uint32_t)((warp_m * 32 + i * 16) * ROWB) + arel;
            ldsm_x4(ah[i], ra);
            ldsm_x4(al[i], ra + ARRB);
        }
        #pragma unroll
        for (int jp = 0; jp < 4; jp++) {
            uint32_t rb = sb + 2 * ARRB +
                (uint32_t)((warp_n * 64 + jp * 16) * ROWB) + brel;
            uint32_t bh[4], bl[4];
            ldsm_x4(bh, rb);
            ldsm_x4(bl, rb + ARRB);
            #pragma unroll
            for (int j2 = 0; j2 < 2; j2++) {
                int jn = jp * 2 + j2;
                #pragma unroll
                for (int i = 0; i < 2; i++) {
                    mma_bf16(acc[i][jn], ah[i], bh[2 * j2], bh[2 * j2 + 1]);
                    mma_bf16(acc[i][jn], ah[i], bl[2 * j2], bl[2 * j2 + 1]);
                    mma_bf16(acc[i][jn], al[i], bh[2 * j2], bh[2 * j2 + 1]);
                }
            }
        }
        __syncthreads();
        if (it + 2 < NC) { fill(s, it + 2); CP_COMMIT(); }
    }

    // ---- epilogue ----
    #pragma unroll
    for (int i = 0; i < 2; i++) {
        #pragma unroll
        for (int jn = 0; jn < 8; jn++) {
            int colb = warp_n * 64 + jn * 8 + (lane & 3) * 2;
            float bb0 = bvec[(size_t)e * NTOT + n0g + colb];
            float bb1 = bvec[(size_t)e * NTOT + n0g + colb + 1];
            #pragma unroll
            for (int rp = 0; rp < 2; rp++) {
                int orow = warp_m * 32 + i * 16 + t4 + 8 * rp;
                int lr = r0 + orow;
                if (lr >= cnt) continue;
                int pair = g_sorted[base + lr];
                float v0 = acc[i][jn][2 * rp]     + bb0;
                float v1 = acc[i][jn][2 * rp + 1] + bb1;
                if (!G2) {
                    v0 = fmaxf(v0, 0.f);
                    v1 = fmaxf(v1, 0.f);
                    float h0 = bf16rt(v0), h1 = bf16rt(v1);
                    size_t o = (size_t)(gbase + orow) * DHID + n0g + colb;
                    *(uint32_t*)&g_hhi[o] = packbf2(h0, h1);
                    *(uint32_t*)&g_hlo[o] = packbf2(v0 - h0, v1 - h1);
                } else {
                    int token = pair >> 1;
                    float wgt = g_wt[pair];
                    float* op = outp + (size_t)token * DOUT + n0g + colb;
                    atomicAdd(op,     wgt * v0);
                    atomicAdd(op + 1, wgt * v1);
                }
            }
        }
    }
}

// ================= launch =================
extern "C" void kernel_launch(void* const* d_in, const int* in_sizes, int n_in,
                              void* d_out, int out_size) {
    const float* x    = (const float*)d_in[0];
    const float* Wg   = (const float*)d_in[1];
    const float* bg   = (const float*)d_in[2];
    const float* W1   = (const float*)d_in[3];
    const float* b1   = (const float*)d_in[4];
    const float* W2   = (const float*)d_in[5];
    const float* b2   = (const float*)d_in[6];
    const float* bias = (const float*)d_in[7];
    float* out = (float*)d_out;

    int write_extra = ((size_t)out_size >= OUT_TOTAL) ? 1 : 0;

    k_reset<<<1, 32>>>();
    k_gating<<<N_TOK / 16, 256>>>(x, Wg, bg, bias, out, write_extra);
    k_scan<<<1, 1>>>();
    k_scatter<<<NP / 256, 256>>>();
    k_zero<<<(N_TOK * DOUT / 4) / 256, 256>>>(out);
    k_xsplit<<<(N_TOK * DIN / 4) / 256, 256>>>(x);
    k_wsplit<<<dim3(DHID / 32, DIN / 32, E_NUM), dim3(32, 8)>>>(W1, DIN, DHID, 0);
    k_wsplit<<<dim3(DOUT / 32, DHID / 32, E_NUM), dim3(32, 8)>>>(W2, DHID, DOUT, 1);

    k_mma_gemm<DIN, DHID, false><<<dim3(DHID / BN, MAXT), 256>>>(b1, nullptr);
    k_mma_gemm<DHID, DOUT, true><<<dim3(DOUT / BN, MAXT), 256>>>(b2, out);
}

// round 13
// speedup vs baseline: 6.5872x; 1.1313x over previous
#include <cuda_runtime.h>
#include <cuda_bf16.h>
#include <math.h>
#include <stdint.h>

#define N_TOK 8192
#define E_NUM 16
#define TOPK 2
#define DIN 1024
#define DHID 4096
#define DOUT 1024
#define NP (N_TOK * TOPK)
#define MAXT 160

#define OUT_GL ((size_t)N_TOK * DOUT)
#define OUT_IDX (OUT_GL + (size_t)N_TOK * E_NUM)
#define OUT_TOTAL (OUT_IDX + (size_t)N_TOK * TOPK)

// ---- GEMM tiling ----
#define BM 128
#define BN 128
#define BK 16
#define PADK 24                 // 48B row stride -> ldmatrix conflict-free
#define ROWB (PADK * 2)
#define ARRB (BM * ROWB)        // 6144 B per array
#define STGB (4 * ARRB)         // 24576 B per stage
#define NSTG 4
#define DYNSM (NSTG * STGB)     // 98304 B dynamic smem

// -------- device scratch (referenced ONLY inside kernels; NEVER passed as args) --------
__device__ __align__(256) __nv_bfloat16 g_xhi[(size_t)N_TOK * DIN];
__device__ __align__(256) __nv_bfloat16 g_xlo[(size_t)N_TOK * DIN];
__device__ __align__(256) __nv_bfloat16 g_hhi[((size_t)NP + BM) * DHID];
__device__ __align__(256) __nv_bfloat16 g_hlo[((size_t)NP + BM) * DHID];
__device__ __align__(256) __nv_bfloat16 g_w1hi[(size_t)E_NUM * DHID * DIN]; // [e][n][k]
__device__ __align__(256) __nv_bfloat16 g_w1lo[(size_t)E_NUM * DHID * DIN];
__device__ __align__(256) __nv_bfloat16 g_w2hi[(size_t)E_NUM * DOUT * DHID];
__device__ __align__(256) __nv_bfloat16 g_w2lo[(size_t)E_NUM * DOUT * DHID];
__device__ int   g_sorted[NP];
__device__ int   g_eid[NP];
__device__ float g_wt[NP];
__device__ int   g_cnt[E_NUM];
__device__ int   g_off[E_NUM + 1];
__device__ int   g_tile_e[MAXT];
__device__ int   g_tile_r[MAXT];
__device__ int   g_ntiles;

// ================= helpers =================
__device__ __forceinline__ uint32_t smem_u32(const void* p) {
    uint32_t a;
    asm("{ .reg .u64 t; cvta.to.shared.u64 t, %1; cvt.u32.u64 %0, t; }"
        : "=r"(a) : "l"(p));
    return a;
}
__device__ __forceinline__ void cpa16(uint32_t dst, const void* src) {
    asm volatile("cp.async.cg.shared.global [%0], [%1], 16;"
                 :: "r"(dst), "l"(src) : "memory");
}
#define CP_COMMIT() asm volatile("cp.async.commit_group;" ::: "memory")
#define CP_WAIT2()  asm volatile("cp.async.wait_group 2;" ::: "memory")

__device__ __forceinline__ void ldsm_x4(uint32_t* r, uint32_t addr) {
    asm volatile("ldmatrix.sync.aligned.m8n8.x4.shared.b16 {%0,%1,%2,%3}, [%4];"
        : "=r"(r[0]), "=r"(r[1]), "=r"(r[2]), "=r"(r[3]) : "r"(addr));
}
__device__ __forceinline__ void mma_bf16(float* c, const uint32_t* a,
                                         uint32_t b0, uint32_t b1) {
    asm volatile(
        "mma.sync.aligned.m16n8k16.row.col.f32.bf16.bf16.f32 "
        "{%0,%1,%2,%3}, {%4,%5,%6,%7}, {%8,%9}, {%0,%1,%2,%3};"
        : "+f"(c[0]), "+f"(c[1]), "+f"(c[2]), "+f"(c[3])
        : "r"(a[0]), "r"(a[1]), "r"(a[2]), "r"(a[3]), "r"(b0), "r"(b1));
}
__device__ __forceinline__ uint32_t packbf2(float a, float b) {
    __nv_bfloat162 t = __floats2bfloat162_rn(a, b);
    return *reinterpret_cast<uint32_t*>(&t);
}
__device__ __forceinline__ float bf16rt(float v) {
    return __bfloat162float(__float2bfloat16(v));
}

// ================= fused prep: zero-out | xsplit | wsplit(W1) | wsplit(W2) =================
#define PZ_ZERO 8192
#define PZ_XSP  8192
#define PZ_W1   65536
#define PZ_W2   65536

__global__ void k_prep(const float* __restrict__ x,
                       const float* __restrict__ W1,
                       const float* __restrict__ W2,
                       float* __restrict__ out) {
    __shared__ float s[32][33];
    int b = blockIdx.x;
    int tid = threadIdx.x;

    if (b < PZ_ZERO) {
        size_t i = (size_t)b * 256 + tid;
        ((float4*)out)[i] = make_float4(0.f, 0.f, 0.f, 0.f);
        return;
    }
    b -= PZ_ZERO;
    if (b < PZ_XSP) {
        size_t i = ((size_t)b * 256 + tid) * 4;
        float4 f = *(const float4*)(x + i);
        float hx = bf16rt(f.x), hy = bf16rt(f.y), hz = bf16rt(f.z), hw = bf16rt(f.w);
        *(uint2*)(g_xhi + i) = make_uint2(packbf2(hx, hy), packbf2(hz, hw));
        *(uint2*)(g_xlo + i) = make_uint2(packbf2(f.x - hx, f.y - hy),
                                          packbf2(f.z - hz, f.w - hw));
        return;
    }
    b -= PZ_XSP;

    const float* W; int K, Nn, bx, by, e; bool w1;
    if (b < PZ_W1) {
        w1 = true;  W = W1; K = DIN;  Nn = DHID;
        bx = b & 127; by = (b >> 7) & 31; e = b >> 12;
    } else {
        b -= PZ_W1;
        w1 = false; W = W2; K = DHID; Nn = DOUT;
        bx = b & 31; by = (b >> 5) & 127; e = b >> 12;
    }
    int k0 = by * 32, n0 = bx * 32;
    int tx = tid & 31, ty = tid >> 5;   // 32 x 8
    const float* Wp = W + (size_t)e * K * Nn;
    #pragma unroll
    for (int i = 0; i < 4; i++)
        s[ty + 8 * i][tx] = Wp[(size_t)(k0 + ty + 8 * i) * Nn + n0 + tx];
    __syncthreads();
    #pragma unroll
    for (int i = 0; i < 4; i++) {
        int n = n0 + ty + 8 * i;
        float v = s[tx][ty + 8 * i];
        float h = bf16rt(v);
        size_t o = ((size_t)e * Nn + n) * K + k0 + tx;
        if (w1) { g_w1hi[o] = __float2bfloat16(h); g_w1lo[o] = __float2bfloat16(v - h); }
        else    { g_w2hi[o] = __float2bfloat16(h); g_w2lo[o] = __float2bfloat16(v - h); }
    }
}

// ================= gating =================
__global__ void k_gating(const float* __restrict__ x,
                         const float* __restrict__ Wg,
                         const float* __restrict__ bg,
                         const float* __restrict__ bias,
                         float* __restrict__ out,
                         int write_extra) {
    __shared__ float sx[16][256];
    __shared__ float slog[16][16];
    __shared__ float sbias[16];

    int tid = threadIdx.x;
    int tl = tid >> 4;
    int e  = tid & 15;
    int tok0 = blockIdx.x * 16;
    int token = tok0 + tl;

    if (tid < E_NUM) sbias[tid] = bias[tid];

    float acc = 0.f;
    for (int k0 = 0; k0 < DIN; k0 += 256) {
        __syncthreads();
        #pragma unroll
        for (int i = 0; i < 4; i++) {
            int lin4 = i * 1024 + tid * 4;
            int row = lin4 >> 8;
            int col = lin4 & 255;
            *(float4*)&sx[row][col] =
                *(const float4*)(x + (size_t)(tok0 + row) * DIN + k0 + col);
        }
        __syncthreads();
        #pragma unroll 8
        for (int k = 0; k < 256; k++)
            acc += sx[tl][k] * Wg[(size_t)(k0 + k) * E_NUM + e];
    }
    acc += bg[e];

    if (write_extra)
        out[OUT_GL + (size_t)token * E_NUM + e] = acc;
    slog[tl][e] = acc;
    __syncthreads();

    if (e == 0) {
        float b0 = -INFINITY; int i0 = 0;
        #pragma unroll
        for (int j = 0; j < E_NUM; j++) {
            float v = slog[tl][j] + sbias[j];
            if (v > b0) { b0 = v; i0 = j; }
        }
        float b1v = -INFINITY; int i1 = 0;
        #pragma unroll
        for (int j = 0; j < E_NUM; j++) {
            if (j == i0) continue;
            float v = slog[tl][j] + sbias[j];
            if (v > b1v) { b1v = v; i1 = j; }
        }
        float l0 = slog[tl][i0], l1 = slog[tl][i1];
        float m = fmaxf(l0, l1);
        float e0 = expf(l0 - m), e1 = expf(l1 - m);
        float inv = 1.f / (e0 + e1);

        int p0 = token * 2, p1 = token * 2 + 1;
        g_eid[p0] = i0; g_wt[p0] = e0 * inv;
        g_eid[p1] = i1; g_wt[p1] = e1 * inv;
        if (write_extra) {
            out[OUT_IDX + p0] = (float)i0;
            out[OUT_IDX + p1] = (float)i1;
        }
    }
}

// ================= fused route (1 block) =================
__global__ void k_route() {
    __shared__ int scnt[E_NUM], scur[E_NUM], soff[E_NUM + 1];
    int tid = threadIdx.x;
    if (tid < E_NUM) scnt[tid] = 0;
    __syncthreads();
    for (int p = tid; p < NP; p += 256)
        atomicAdd(&scnt[g_eid[p]], 1);
    __syncthreads();
    if (tid == 0) {
        int off = 0;
        soff[0] = 0; g_off[0] = 0;
        for (int e = 0; e < E_NUM; e++) {
            g_cnt[e] = scnt[e];
            off += scnt[e];
            soff[e + 1] = off; g_off[e + 1] = off;
        }
        int nt = 0;
        for (int e = 0; e < E_NUM; e++)
            for (int r = 0; r < scnt[e]; r += BM)
                if (nt < MAXT) { g_tile_e[nt] = e; g_tile_r[nt] = r; nt++; }
        g_ntiles = nt;
    }
    __syncthreads();
    if (tid < E_NUM) scur[tid] = soff[tid];
    __syncthreads();
    for (int p = tid; p < NP; p += 256) {
        int e = g_eid[p];
        int pos = atomicAdd(&scur[e], 1);
        g_sorted[pos] = p;
    }
}

// ===== grouped GEMM: 4-stage cp.async (commit EVERY iter), 1 barrier/iter =====
template <int KTOT, int NTOT, bool G2>
__global__ void __launch_bounds__(256, 2)
k_mma_gemm(const float* __restrict__ bvec, float* __restrict__ outp) {
    int tm = blockIdx.y;
    if (tm >= g_ntiles) return;

    extern __shared__ __nv_bfloat16 dsm[];
    uint32_t smb = smem_u32(dsm);

    int tid = threadIdx.x, lane = tid & 31, w = tid >> 5;
    int warp_m = w & 3, warp_n = w >> 2;

    int e = g_tile_e[tm], r0 = g_tile_r[tm];
    int base = g_off[e], cnt = g_cnt[e];
    int gbase = base + r0;
    int n0g = blockIdx.x * BN;

    // ---- staging ----
    int row = tid >> 1, oct = tid & 1;
    const __nv_bfloat16* Ahi = G2 ? g_hhi : g_xhi;
    const __nv_bfloat16* Alo = G2 ? g_hlo : g_xlo;
    const __nv_bfloat16* Bhi = G2 ? g_w2hi : g_w1hi;
    const __nv_bfloat16* Blo = G2 ? g_w2lo : g_w1lo;

    size_t abase;
    if (G2) {
        abase = (size_t)(gbase + row) * KTOT;
    } else {
        int lr = r0 + row;
        int p = (lr < cnt) ? g_sorted[base + lr] : -1;
        abase = (size_t)((p >= 0) ? (p >> 1) : 0) * KTOT;
    }
    size_t bbase = ((size_t)e * NTOT + n0g + row) * KTOT;
    uint32_t dstoff = (uint32_t)(row * ROWB + oct * 16);

    auto fill = [&](int s, int it) {
        uint32_t sb = smb + s * STGB;
        size_t ko = (size_t)it * BK + oct * 8;
        cpa16(sb + 0 * ARRB + dstoff, Ahi + abase + ko);
        cpa16(sb + 1 * ARRB + dstoff, Alo + abase + ko);
        cpa16(sb + 2 * ARRB + dstoff, Bhi + bbase + ko);
        cpa16(sb + 3 * ARRB + dstoff, Blo + bbase + ko);
    };

    float acc[2][8][4] = {};
    const int NC = KTOT / BK;

    fill(0, 0); CP_COMMIT();
    fill(1, 1); CP_COMMIT();
    fill(2, 2); CP_COMMIT();

    // ldmatrix lane-relative offsets
    int lq = lane >> 3, lr8 = lane & 7;
    uint32_t arel = (uint32_t)((lr8 + (lq & 1) * 8) * ROWB + (lq >> 1) * 16);
    uint32_t brel = (uint32_t)((lr8 + (lq >> 1) * 8) * ROWB + (lq & 1) * 16);
    int t4 = lane >> 2;

    for (int it = 0; it < NC; it++) {
        int s = it & 3;
        CP_WAIT2();
        __syncthreads();

        uint32_t sb = smb + s * STGB;
        uint32_t ah[2][4], al[2][4];
        #pragma unroll
        for (int i = 0; i < 2; i++) {
            uint32_t ra = sb + (uint32_t)((warp_m * 32 + i * 16) * ROWB) + arel;
            ldsm_x4(ah[i], ra);
            ldsm_x4(al[i], ra + ARRB);
        }
        #pragma unroll
        for (int jp = 0; jp < 4; jp++) {
            uint32_t rb = sb + 2 * ARRB +
                (uint32_t)((warp_n * 64 + jp * 16) * ROWB) + brel;
            uint32_t bh[4], bl[4];
            ldsm_x4(bh, rb);
            ldsm_x4(bl, rb + ARRB);
            #pragma unroll
            for (int j2 = 0; j2 < 2; j2++) {
                int jn = jp * 2 + j2;
                #pragma unroll
                for (int i = 0; i < 2; i++) {
                    mma_bf16(acc[i][jn], ah[i], bh[2 * j2], bh[2 * j2 + 1]);
                    mma_bf16(acc[i][jn], ah[i], bl[2 * j2], bl[2 * j2 + 1]);
                    mma_bf16(acc[i][jn], al[i], bh[2 * j2], bh[2 * j2 + 1]);
                }
            }
        }
        // FIX: commit every iteration (empty groups in the tail) so CP_WAIT2
        // always guarantees the stage consumed at iteration it+1 has landed.
        if (it + 3 < NC) fill((it + 3) & 3, it + 3);
        CP_COMMIT();
    }

    // ---- epilogue ----
    #pragma unroll
    for (int i = 0; i < 2; i++) {
        #pragma unroll
        for (int jn = 0; jn < 8; jn++) {
            int colb = warp_n * 64 + jn * 8 + (lane & 3) * 2;
            float bb0 = bvec[(size_t)e * NTOT + n0g + colb];
            float bb1 = bvec[(size_t)e * NTOT + n0g + colb + 1];
            #pragma unroll
            for (int rp = 0; rp < 2; rp++) {
                int orow = warp_m * 32 + i * 16 + t4 + 8 * rp;
                int lr = r0 + orow;
                if (lr >= cnt) continue;
                int pair = g_sorted[base + lr];
                float v0 = acc[i][jn][2 * rp]     + bb0;
                float v1 = acc[i][jn][2 * rp + 1] + bb1;
                if (!G2) {
                    v0 = fmaxf(v0, 0.f);
                    v1 = fmaxf(v1, 0.f);
                    float h0 = bf16rt(v0), h1 = bf16rt(v1);
                    size_t o = (size_t)(gbase + orow) * DHID + n0g + colb;
                    *(uint32_t*)&g_hhi[o] = packbf2(h0, h1);
                    *(uint32_t*)&g_hlo[o] = packbf2(v0 - h0, v1 - h1);
                } else {
                    int token = pair >> 1;
                    float wgt = g_wt[pair];
                    float* op = outp + (size_t)token * DOUT + n0g + colb;
                    atomicAdd(op,     wgt * v0);
                    atomicAdd(op + 1, wgt * v1);
                }
            }
        }
    }
}

// ================= launch =================
extern "C" void kernel_launch(void* const* d_in, const int* in_sizes, int n_in,
                              void* d_out, int out_size) {
    const float* x    = (const float*)d_in[0];
    const float* Wg   = (const float*)d_in[1];
    const float* bg   = (const float*)d_in[2];
    const float* W1   = (const float*)d_in[3];
    const float* b1   = (const float*)d_in[4];
    const float* W2   = (const float*)d_in[5];
    const float* b2   = (const float*)d_in[6];
    const float* bias = (const float*)d_in[7];
    float* out = (float*)d_out;

    int write_extra = ((size_t)out_size >= OUT_TOTAL) ? 1 : 0;

    cudaFuncSetAttribute(k_mma_gemm<DIN, DHID, false>,
                         cudaFuncAttributeMaxDynamicSharedMemorySize, DYNSM);
    cudaFuncSetAttribute(k_mma_gemm<DHID, DOUT, true>,
                         cudaFuncAttributeMaxDynamicSharedMemorySize, DYNSM);

    k_prep<<<PZ_ZERO + PZ_XSP + PZ_W1 + PZ_W2, 256>>>(x, W1, W2, out);
    k_gating<<<N_TOK / 16, 256>>>(x, Wg, bg, bias, out, write_extra);
    k_route<<<1, 256>>>();
    k_mma_gemm<DIN, DHID, false><<<dim3(DHID / BN, MAXT), 256, DYNSM>>>(b1, nullptr);
    k_mma_gemm<DHID, DOUT, true><<<dim3(DOUT / BN, MAXT), 256, DYNSM>>>(b2, out);
}